// round 13
// baseline (speedup 1.0000x reference)
#include <cuda_runtime.h>

#define BB   8
#define LL   384
#define HH   512
#define NHH  8
#define DHH  64
#define MS   384
#define RROWS 769

// ---------------- scratch (device globals; no allocation allowed) ----------------
__device__ float g_qu [BB*LL*HH];
__device__ float g_qv [BB*LL*HH];
__device__ float g_k  [BB*LL*HH];
__device__ float g_vT [BB*NHH*DHH*LL];
__device__ float g_ctx[BB*LL*HH];
__device__ float g_R  [RROWS*HH];
__device__ float g_S  [BB*NHH*LL*LL];
__device__ float g_qR [BB*NHH*LL*RROWS];
// rounded copies of raw inputs
__device__ float g_qin[BB*LL*HH];
__device__ float g_kin[BB*LL*HH];
__device__ float g_vin[BB*LL*HH];
__device__ float g_pe [RROWS*HH];
__device__ float g_Wq [HH*HH];
__device__ float g_Wk [HH*HH];
__device__ float g_Wv [HH*HH];
__device__ float g_Wr [HH*HH];
__device__ float g_Wff[HH*HH];

// ---------------- helpers ----------------
__device__ __forceinline__ float tf32r(float x) {
    unsigned u;
    asm("cvt.rna.tf32.f32 %0, %1;" : "=r"(u) : "f"(x));
    return __uint_as_float(u);
}

__device__ __forceinline__ void mma_tf32(float c[4],
                                         unsigned a0, unsigned a1, unsigned a2, unsigned a3,
                                         unsigned b0, unsigned b1)
{
    asm volatile(
        "mma.sync.aligned.m16n8k8.row.col.f32.tf32.tf32.f32 "
        "{%0,%1,%2,%3},{%4,%5,%6,%7},{%8,%9},{%0,%1,%2,%3};\n"
        : "+f"(c[0]), "+f"(c[1]), "+f"(c[2]), "+f"(c[3])
        : "r"(a0), "r"(a1), "r"(a2), "r"(a3), "r"(b0), "r"(b1));
}

__device__ __forceinline__ void cp16(unsigned dst, const void* src, bool pred) {
    int sz = pred ? 16 : 0;
    asm volatile("cp.async.cg.shared.global [%0], [%1], 16, %2;\n"
                 :: "r"(dst), "l"(src), "r"(sz));
}

// ---------------- pre-round pass: fp32 -> tf32(rna) copies ----------------
struct RSeg { const float* src; float* dst; int n4; };
struct RPack { RSeg s[9]; };

__global__ void round_inputs(RPack P)
{
    int idx = blockIdx.x * blockDim.x + threadIdx.x;
#pragma unroll
    for (int i = 0; i < 9; ++i) {
        if (idx < P.s[i].n4) {
            float4 v = ((const float4*)P.s[i].src)[idx];
            v.x = tf32r(v.x); v.y = tf32r(v.y); v.z = tf32r(v.z); v.w = tf32r(v.w);
            ((float4*)P.s[i].dst)[idx] = v;
            return;
        }
        idx -= P.s[i].n4;
    }
}

// ---------------- descriptor pack ----------------
// mode: 0 normal, 1 transC (v->vT), 2 qdual (write qu & qv with u/v biases)
struct GDesc {
    const float* A; const float* B; const float* bias; float* C;
    float* C2; const float* biasU; const float* biasV;
    int M, N, K, lda, ldb, ldc;
    long long Ao, Ai, Bo, Bi, Co, Ci;
    int bdiv;
    int zcount;
    int roundC;
    int mode;
    int skewB;
};
struct GPack { GDesc d[4]; };

// ---------------- tf32 tensor-core NT GEMM, parameterized pipeline ----------------
template<int BM, int BN, int WM, int WN, int BK, int STAGES>
__global__ void __launch_bounds__(256, 2)
gemm_tc(GPack P)
{
    constexpr int LDS_S = BK + 4;
    constexpr int WGM   = BM / WM;
    constexpr int MI    = WM / 16;
    constexpr int NI    = WN / 8;
    constexpr int CPR   = BK / 4;                 // float4 chunks per row
    constexpr int ACH   = BM * CPR / 256;
    constexpr int BCH   = BN * CPR / 256;
    static_assert(WGM * (BN / WN) == 8, "8 warps");
    static_assert(BM * CPR % 256 == 0 && BN * CPR % 256 == 0, "even chunks");

    extern __shared__ float sm[];
    float* Asm = sm;
    float* Bsm = sm + STAGES * BM * LDS_S;
    unsigned sb  = (unsigned)__cvta_generic_to_shared(sm);
    unsigned sbB = sb + (unsigned)STAGES * BM * LDS_S * 4u;

    int zz = blockIdx.z;
    int di = 0;
    while (zz >= P.d[di].zcount) { zz -= P.d[di].zcount; ++di; }
    GDesc D = P.d[di];

    int bm = blockIdx.y * BM;
    int bn = blockIdx.x * BN;
    if (bm >= D.M || bn >= D.N) return;
    if (D.skewB) {
        int s = bm + bn;
        if (s + BM + BN - 2 < MS || s > MS + LL - 1) return;
    }

    const float* A = D.A + (long long)(zz / D.bdiv) * D.Ao + (long long)(zz % D.bdiv) * D.Ai;
    const float* B = D.B + (long long)(zz / D.bdiv) * D.Bo + (long long)(zz % D.bdiv) * D.Bi;
    float*       C = D.C + (long long)(zz / D.bdiv) * D.Co + (long long)(zz % D.bdiv) * D.Ci;
    float*       C2 = D.C2;

    int tid  = threadIdx.x;
    int lane = tid & 31;
    int wid  = tid >> 5;
    int wm   = (wid % WGM) * WM;
    int wn   = (wid / WGM) * WN;
    int r0   = lane >> 2;
    int c0   = lane & 3;

    float acc[MI][NI][4];
#pragma unroll
    for (int mi = 0; mi < MI; ++mi)
#pragma unroll
        for (int ni = 0; ni < NI; ++ni)
#pragma unroll
            for (int t = 0; t < 4; ++t) acc[mi][ni][t] = 0.f;

#define LOADSTAGE(T, BUF)                                                             \
    {                                                                                 \
        int kb = (T) * BK;                                                            \
        _Pragma("unroll")                                                             \
        for (int i = 0; i < ACH; ++i) {                                               \
            int e = tid + i * 256;                                                    \
            int row = e / CPR, kc = (e % CPR) * 4;                                    \
            bool p = (bm + row) < D.M;                                                \
            const float* src = A + (long long)(bm + row) * D.lda + kb + kc;           \
            unsigned dst = sb + (((BUF) * BM + row) * LDS_S + kc) * 4u;               \
            cp16(dst, src, p);                                                        \
        }                                                                             \
        _Pragma("unroll")                                                             \
        for (int i = 0; i < BCH; ++i) {                                               \
            int e = tid + i * 256;                                                    \
            int row = e / CPR, kc = (e % CPR) * 4;                                    \
            bool p = (bn + row) < D.N;                                                \
            const float* src = B + (long long)(bn + row) * D.ldb + kb + kc;           \
            unsigned dst = sbB + (((BUF) * BN + row) * LDS_S + kc) * 4u;              \
            cp16(dst, src, p);                                                        \
        }                                                                             \
        asm volatile("cp.async.commit_group;\n");                                     \
    }

#define MATH(BUF)                                                                     \
    _Pragma("unroll")                                                                 \
    for (int kk = 0; kk < BK; kk += 8) {                                              \
        unsigned a[MI][4], b[NI][2];                                                  \
        _Pragma("unroll")                                                             \
        for (int mi = 0; mi < MI; ++mi) {                                             \
            int m0 = wm + mi * 16 + r0;                                               \
            const unsigned* ap0 = (const unsigned*)(Asm + ((BUF) * BM + m0) * LDS_S + kk + c0);      \
            const unsigned* ap1 = (const unsigned*)(Asm + ((BUF) * BM + m0 + 8) * LDS_S + kk + c0);  \
            a[mi][0] = ap0[0];                                                        \
            a[mi][1] = ap1[0];                                                        \
            a[mi][2] = ap0[4];                                                        \
            a[mi][3] = ap1[4];                                                        \
        }                                                                             \
        _Pragma("unroll")                                                             \
        for (int ni = 0; ni < NI; ++ni) {                                             \
            int n0 = wn + ni * 8 + r0;                                                \
            const unsigned* bp = (const unsigned*)(Bsm + ((BUF) * BN + n0) * LDS_S + kk + c0);       \
            b[ni][0] = bp[0];                                                         \
            b[ni][1] = bp[4];                                                         \
        }                                                                             \
        _Pragma("unroll")                                                             \
        for (int mi = 0; mi < MI; ++mi)                                               \
            _Pragma("unroll")                                                         \
            for (int ni = 0; ni < NI; ++ni)                                           \
                mma_tf32(acc[mi][ni], a[mi][0], a[mi][1], a[mi][2], a[mi][3],         \
                         b[ni][0], b[ni][1]);                                         \
    }

    int nt = D.K / BK;

    // prologue: fill STAGES-1 stages
#pragma unroll
    for (int s = 0; s < STAGES - 1; ++s) {
        if (s < nt) LOADSTAGE(s, s)
    }

    for (int t = 0; t < nt; ++t) {
        int lt = t + STAGES - 1;
        if (lt < nt) {
            LOADSTAGE(lt, lt % STAGES)
        } else {
            asm volatile("cp.async.commit_group;\n");   // keep group count uniform
        }
        asm volatile("cp.async.wait_group %0;\n" :: "n"(STAGES - 1));
        __syncthreads();
        MATH(t % STAGES)
        __syncthreads();
    }

    // epilogue
#pragma unroll
    for (int mi = 0; mi < MI; ++mi) {
#pragma unroll
        for (int ni = 0; ni < NI; ++ni) {
            int cA = bn + wn + ni * 8 + c0 * 2;
            float b0 = 0.f, b1 = 0.f;
            if (D.bias) {
                if (cA < D.N)     b0 = D.bias[cA];
                if (cA + 1 < D.N) b1 = D.bias[cA + 1];
            }
#pragma unroll
            for (int half = 0; half < 2; ++half) {
                int r = bm + wm + mi * 16 + r0 + half * 8;
                if (r >= D.M) continue;
                float v0 = acc[mi][ni][half * 2]     + b0;
                float v1 = acc[mi][ni][half * 2 + 1] + b1;
                if (D.mode == 2) {
                    if (cA < D.N) {
                        C [(long long)r * D.ldc + cA] = tf32r(v0 + D.biasU[cA]);
                        C2[(long long)r * D.ldc + cA] = tf32r(v0 + D.biasV[cA]);
                    }
                    if (cA + 1 < D.N) {
                        C [(long long)r * D.ldc + cA + 1] = tf32r(v1 + D.biasU[cA + 1]);
                        C2[(long long)r * D.ldc + cA + 1] = tf32r(v1 + D.biasV[cA + 1]);
                    }
                } else {
                    if (D.roundC) { v0 = tf32r(v0); v1 = tf32r(v1); }
                    if (D.mode == 1) {
                        long long base = (long long)(r / LL) * HH;
                        int j = r % LL;
                        if (cA < D.N)     C[(base + cA) * LL + j]     = v0;
                        if (cA + 1 < D.N) C[(base + cA + 1) * LL + j] = v1;
                    } else {
                        if (cA < D.N)     C[(long long)r * D.ldc + cA]     = v0;
                        if (cA + 1 < D.N) C[(long long)r * D.ldc + cA + 1] = v1;
                    }
                }
            }
        }
    }
#undef LOADSTAGE
#undef MATH
}

// ---------------- softmax: merge S + shifted qR, scale+mask+exp+norm ----------------
__global__ void softmax_kernel(const int* __restrict__ seq_len)
{
    int bid = blockIdx.x;                 // (b*NH + h)*L + i
    int i = bid % LL;
    int b = bid / (LL * NHH);
    int tid = threadIdx.x;

    float*       Srow  = g_S  + (long long)bid * LL;
    const float* qRrow = g_qR + (long long)bid * RROWS + (MS - i);  // index by j directly
    int sl = seq_len[b];

    float s[3];
    float m = -1e30f;
#pragma unroll
    for (int r = 0; r < 3; ++r) {
        int j = tid + r * 128;
        float v = (Srow[j] + qRrow[j]) * 0.125f;
        if (j >= sl) v = -1e30f;
        s[r] = v;
        m = fmaxf(m, v);
    }
    __shared__ float redm[4];
#pragma unroll
    for (int off = 16; off > 0; off >>= 1) m = fmaxf(m, __shfl_xor_sync(0xffffffffu, m, off));
    if ((tid & 31) == 0) redm[tid >> 5] = m;
    __syncthreads();
    m = fmaxf(fmaxf(redm[0], redm[1]), fmaxf(redm[2], redm[3]));

    float sum = 0.f;
#pragma unroll
    for (int r = 0; r < 3; ++r) { s[r] = __expf(s[r] - m); sum += s[r]; }
#pragma unroll
    for (int off = 16; off > 0; off >>= 1) sum += __shfl_xor_sync(0xffffffffu, sum, off);
    __shared__ float reds[4];
    if ((tid & 31) == 0) reds[tid >> 5] = sum;
    __syncthreads();
    sum = reds[0] + reds[1] + reds[2] + reds[3];
    float inv = 1.f / sum;
#pragma unroll
    for (int r = 0; r < 3; ++r) Srow[tid + r * 128] = tf32r(s[r] * inv);
}

// ------------------------------------ launch ------------------------------------------
extern "C" void kernel_launch(void* const* d_in, const int* in_sizes, int n_in,
                              void* d_out, int out_size)
{
    const float* key    = (const float*)d_in[0];
    const float* query  = (const float*)d_in[1];
    const float* value  = (const float*)d_in[2];
    const int*   seqlen = (const int*)  d_in[3];
    const float* pe     = (const float*)d_in[4];
    const float* Wk = (const float*)d_in[5];  const float* bk = (const float*)d_in[6];
    const float* Wq = (const float*)d_in[7];  const float* bq = (const float*)d_in[8];
    const float* Wv = (const float*)d_in[9];  const float* bv = (const float*)d_in[10];
    const float* Wr = (const float*)d_in[11]; const float* br = (const float*)d_in[12];
    const float* u_bias = (const float*)d_in[13];
    const float* v_bias = (const float*)d_in[14];
    const float* Wff = (const float*)d_in[15]; const float* bff = (const float*)d_in[16];
    float* out = (float*)d_out;

    float *qu_, *qv_, *k_, *vT_, *ctx_, *R_, *S_, *qR_;
    float *qin_, *kin_, *vin_, *pe_, *Wq_, *Wk_, *Wv_, *Wr_, *Wff_;
    cudaGetSymbolAddress((void**)&qu_,  g_qu);
    cudaGetSymbolAddress((void**)&qv_,  g_qv);
    cudaGetSymbolAddress((void**)&k_,   g_k);
    cudaGetSymbolAddress((void**)&vT_,  g_vT);
    cudaGetSymbolAddress((void**)&ctx_, g_ctx);
    cudaGetSymbolAddress((void**)&R_,   g_R);
    cudaGetSymbolAddress((void**)&S_,   g_S);
    cudaGetSymbolAddress((void**)&qR_,  g_qR);
    cudaGetSymbolAddress((void**)&qin_, g_qin);
    cudaGetSymbolAddress((void**)&kin_, g_kin);
    cudaGetSymbolAddress((void**)&vin_, g_vin);
    cudaGetSymbolAddress((void**)&pe_,  g_pe);
    cudaGetSymbolAddress((void**)&Wq_,  g_Wq);
    cudaGetSymbolAddress((void**)&Wk_,  g_Wk);
    cudaGetSymbolAddress((void**)&Wv_,  g_Wv);
    cudaGetSymbolAddress((void**)&Wr_,  g_Wr);
    cudaGetSymbolAddress((void**)&Wff_, g_Wff);

    const int M = BB * LL;   // 3072
    const size_t SH_PROJ = (size_t)3 * (128 + 128) * 36 * 4;  // 110592 (3-stage BK=32)
    const size_t SH_ABT  = (size_t)1 * (128 + 128) * 68 * 4;  // 69632  (1-stage BK=64)
    const size_t SH_AV   = (size_t)2 * (64 + 64)   * 36 * 4;  // 36864  (2-stage BK=32)
    const size_t SH_FF   = (size_t)3 * (64 + 128)  * 36 * 4;  // 82944  (3-stage BK=32)

    static bool attr_done = false;
    if (!attr_done) {
        cudaFuncSetAttribute(gemm_tc<128,128,64,32,32,3>,
                             cudaFuncAttributeMaxDynamicSharedMemorySize, (int)SH_PROJ);
        cudaFuncSetAttribute(gemm_tc<128,128,64,32,64,1>,
                             cudaFuncAttributeMaxDynamicSharedMemorySize, (int)SH_ABT);
        cudaFuncSetAttribute(gemm_tc<64,64,32,16,32,2>,
                             cudaFuncAttributeMaxDynamicSharedMemorySize, (int)SH_AV);
        cudaFuncSetAttribute(gemm_tc<64,128,32,32,32,3>,
                             cudaFuncAttributeMaxDynamicSharedMemorySize, (int)SH_FF);
        attr_done = true;
    }

    // ---- 0) round all fp32 inputs to tf32 once ----
    {
        const int NXL = BB * LL * HH / 4;
        const int NPE = RROWS * HH / 4;
        const int NW  = HH * HH / 4;
        RPack P;
        P.s[0] = { query, qin_, NXL };
        P.s[1] = { key,   kin_, NXL };
        P.s[2] = { value, vin_, NXL };
        P.s[3] = { pe,    pe_,  NPE };
        P.s[4] = { Wq,    Wq_,  NW  };
        P.s[5] = { Wk,    Wk_,  NW  };
        P.s[6] = { Wv,    Wv_,  NW  };
        P.s[7] = { Wr,    Wr_,  NW  };
        P.s[8] = { Wff,   Wff_, NW  };
        int tot = 3 * NXL + NPE + 5 * NW;
        round_inputs<<<(tot + 255) / 256, 256>>>(P);
    }

    // ---- 1) projections: qu/qv (dual epilogue), k, vT (trans), R  (3-stage) ----
    {
        GPack P;
        P.d[0] = { qin_, Wq_, bq, qu_, qv_, u_bias, v_bias,
                   M, HH, HH, HH, HH, HH, 0,0,0,0,0,0, 1, 1, 0, 2, 0 };
        P.d[1] = { kin_, Wk_, bk, k_,  nullptr, nullptr, nullptr,
                   M, HH, HH, HH, HH, HH, 0,0,0,0,0,0, 1, 1, 1, 0, 0 };
        P.d[2] = { vin_, Wv_, bv, vT_, nullptr, nullptr, nullptr,
                   M, HH, HH, HH, HH, HH, 0,0,0,0,0,0, 1, 1, 1, 1, 0 };
        P.d[3] = { pe_,  Wr_, br, R_,  nullptr, nullptr, nullptr,
                   RROWS, HH, HH, HH, HH, HH, 0,0,0,0,0,0, 1, 1, 1, 0, 0 };
        dim3 g(HH / 128, (M + 127) / 128, 4);
        gemm_tc<128,128,64,32,32,3><<<g, 256, SH_PROJ>>>(P);
    }

    // ---- 2) A+C term and Bt+D term in one packed launch (single-stage BK=64) ----
    {
        GPack P;
        P.d[0] = { qu_, k_, nullptr, S_, nullptr, nullptr, nullptr,
                   LL, LL, DHH, HH, HH, LL,
                   (long long)LL * HH, DHH,
                   (long long)LL * HH, DHH,
                   (long long)NHH * LL * LL, (long long)LL * LL,
                   NHH, BB * NHH, 0, 0, 0 };
        P.d[1] = { qv_, R_, nullptr, qR_, nullptr, nullptr, nullptr,
                   LL, RROWS, DHH, HH, HH, RROWS,
                   (long long)LL * HH, DHH,
                   0, DHH,
                   (long long)NHH * LL * RROWS, (long long)LL * RROWS,
                   NHH, BB * NHH, 0, 0, 1 };
        P.d[2] = P.d[1]; P.d[3] = P.d[1];
        dim3 g((RROWS + 127) / 128, LL / 128, 2 * BB * NHH);
        gemm_tc<128,128,64,32,64,1><<<g, 256, SH_ABT>>>(P);
    }

    // ---- 3) softmax (S + shifted qR, scale+mask+exp+norm, round attn) ----
    softmax_kernel<<<BB * NHH * LL, 128>>>(seqlen);

    // ---- 4) AV: ctx = attn @ v_h  (BM=64 -> 384 CTAs) ----
    {
        GPack P;
        P.d[0] = { S_, vT_, nullptr, ctx_, nullptr, nullptr, nullptr,
                   LL, DHH, LL, LL, LL, HH,
                   (long long)NHH * LL * LL, (long long)LL * LL,
                   (long long)NHH * DHH * LL, (long long)DHH * LL,
                   (long long)LL * HH, DHH,
                   NHH, BB * NHH, 1, 0, 0 };
        P.d[1] = P.d[0]; P.d[2] = P.d[0]; P.d[3] = P.d[0];
        dim3 g(1, LL / 64, BB * NHH);
        gemm_tc<64,64,32,16,32,2><<<g, 256, SH_AV>>>(P);
    }

    // ---- 5) final FF: out = ctx @ Wff.T + bff (3-stage, 192 CTAs) ----
    {
        GPack P;
        P.d[0] = { ctx_, Wff_, bff, out, nullptr, nullptr, nullptr,
                   M, HH, HH, HH, HH, HH, 0,0,0,0,0,0, 1, 1, 0, 0, 0 };
        P.d[1] = P.d[0]; P.d[2] = P.d[0]; P.d[3] = P.d[0];
        dim3 g(HH / 128, (M + 63) / 64, 1);
        gemm_tc<64,128,32,32,32,3><<<g, 256, SH_FF>>>(P);
    }
}

// round 14
// speedup vs baseline: 1.0199x; 1.0199x over previous
#include <cuda_runtime.h>

#define BB   8
#define LL   384
#define HH   512
#define NHH  8
#define DHH  64
#define MS   384
#define RROWS 769

// ---------------- scratch (device globals; no allocation allowed) ----------------
__device__ float g_qu [BB*LL*HH];
__device__ float g_qv [BB*LL*HH];
__device__ float g_k  [BB*LL*HH];
__device__ float g_vT [BB*NHH*DHH*LL];
__device__ float g_ctx[BB*LL*HH];
__device__ float g_R  [RROWS*HH];
__device__ float g_S  [BB*NHH*LL*LL];
__device__ float g_qR [BB*NHH*LL*RROWS];
// rounded copies of raw inputs
__device__ float g_qin[BB*LL*HH];
__device__ float g_kin[BB*LL*HH];
__device__ float g_vin[BB*LL*HH];
__device__ float g_pe [RROWS*HH];
__device__ float g_Wq [HH*HH];
__device__ float g_Wk [HH*HH];
__device__ float g_Wv [HH*HH];
__device__ float g_Wr [HH*HH];
__device__ float g_Wff[HH*HH];

// ---------------- helpers ----------------
__device__ __forceinline__ float tf32r(float x) {
    unsigned u;
    asm("cvt.rna.tf32.f32 %0, %1;" : "=r"(u) : "f"(x));
    return __uint_as_float(u);
}

__device__ __forceinline__ void mma_tf32(float c[4],
                                         unsigned a0, unsigned a1, unsigned a2, unsigned a3,
                                         unsigned b0, unsigned b1)
{
    asm volatile(
        "mma.sync.aligned.m16n8k8.row.col.f32.tf32.tf32.f32 "
        "{%0,%1,%2,%3},{%4,%5,%6,%7},{%8,%9},{%0,%1,%2,%3};\n"
        : "+f"(c[0]), "+f"(c[1]), "+f"(c[2]), "+f"(c[3])
        : "r"(a0), "r"(a1), "r"(a2), "r"(a3), "r"(b0), "r"(b1));
}

__device__ __forceinline__ void cp16(unsigned dst, const void* src, bool pred) {
    int sz = pred ? 16 : 0;
    asm volatile("cp.async.cg.shared.global [%0], [%1], 16, %2;\n"
                 :: "r"(dst), "l"(src), "r"(sz));
}

// ---------------- pre-round pass: fp32 -> tf32(rna) copies ----------------
struct RSeg { const float* src; float* dst; int n4; };
struct RPack { RSeg s[9]; };

__global__ void round_inputs(RPack P)
{
    int idx = blockIdx.x * blockDim.x + threadIdx.x;
#pragma unroll
    for (int i = 0; i < 9; ++i) {
        if (idx < P.s[i].n4) {
            float4 v = ((const float4*)P.s[i].src)[idx];
            v.x = tf32r(v.x); v.y = tf32r(v.y); v.z = tf32r(v.z); v.w = tf32r(v.w);
            ((float4*)P.s[i].dst)[idx] = v;
            return;
        }
        idx -= P.s[i].n4;
    }
}

// ---------------- descriptor pack ----------------
// mode: 0 normal, 1 transC (v->vT), 2 qdual (write qu & qv with u/v biases)
struct GDesc {
    const float* A; const float* B; const float* bias; float* C;
    float* C2; const float* biasU; const float* biasV;
    int M, N, K, lda, ldb, ldc;
    long long Ao, Ai, Bo, Bi, Co, Ci;
    int bdiv;
    int zcount;
    int roundC;
    int mode;
    int skewB;
};
struct GPack { GDesc d[4]; };

// ---------------- tf32 tensor-core NT GEMM, parameterized pipeline ----------------
template<int BM, int BN, int WM, int WN, int BK, int STAGES>
__global__ void __launch_bounds__(256, 2)
gemm_tc(GPack P)
{
    constexpr int LDS_S = BK + 4;
    constexpr int WGM   = BM / WM;
    constexpr int MI    = WM / 16;
    constexpr int NI    = WN / 8;
    constexpr int CPR   = BK / 4;
    constexpr int ACH   = BM * CPR / 256;
    constexpr int BCH   = BN * CPR / 256;
    static_assert(WGM * (BN / WN) == 8, "8 warps");
    static_assert(BM * CPR % 256 == 0 && BN * CPR % 256 == 0, "even chunks");

    extern __shared__ float sm[];
    float* Asm = sm;
    float* Bsm = sm + STAGES * BM * LDS_S;
    unsigned sb  = (unsigned)__cvta_generic_to_shared(sm);
    unsigned sbB = sb + (unsigned)STAGES * BM * LDS_S * 4u;

    int zz = blockIdx.z;
    int di = 0;
    while (zz >= P.d[di].zcount) { zz -= P.d[di].zcount; ++di; }
    GDesc D = P.d[di];

    int bm = blockIdx.y * BM;
    int bn = blockIdx.x * BN;
    if (bm >= D.M || bn >= D.N) return;
    if (D.skewB) {
        int s = bm + bn;
        if (s + BM + BN - 2 < MS || s > MS + LL - 1) return;
    }

    const float* A = D.A + (long long)(zz / D.bdiv) * D.Ao + (long long)(zz % D.bdiv) * D.Ai;
    const float* B = D.B + (long long)(zz / D.bdiv) * D.Bo + (long long)(zz % D.bdiv) * D.Bi;
    float*       C = D.C + (long long)(zz / D.bdiv) * D.Co + (long long)(zz % D.bdiv) * D.Ci;
    float*       C2 = D.C2;

    int tid  = threadIdx.x;
    int lane = tid & 31;
    int wid  = tid >> 5;
    int wm   = (wid % WGM) * WM;
    int wn   = (wid / WGM) * WN;
    int r0   = lane >> 2;
    int c0   = lane & 3;

    float acc[MI][NI][4];
#pragma unroll
    for (int mi = 0; mi < MI; ++mi)
#pragma unroll
        for (int ni = 0; ni < NI; ++ni)
#pragma unroll
            for (int t = 0; t < 4; ++t) acc[mi][ni][t] = 0.f;

#define LOADSTAGE(T, BUF)                                                             \
    {                                                                                 \
        int kb = (T) * BK;                                                            \
        _Pragma("unroll")                                                             \
        for (int i = 0; i < ACH; ++i) {                                               \
            int e = tid + i * 256;                                                    \
            int row = e / CPR, kc = (e % CPR) * 4;                                    \
            bool p = (bm + row) < D.M;                                                \
            const float* src = A + (long long)(bm + row) * D.lda + kb + kc;           \
            unsigned dst = sb + (((BUF) * BM + row) * LDS_S + kc) * 4u;               \
            cp16(dst, src, p);                                                        \
        }                                                                             \
        _Pragma("unroll")                                                             \
        for (int i = 0; i < BCH; ++i) {                                               \
            int e = tid + i * 256;                                                    \
            int row = e / CPR, kc = (e % CPR) * 4;                                    \
            bool p = (bn + row) < D.N;                                                \
            const float* src = B + (long long)(bn + row) * D.ldb + kb + kc;           \
            unsigned dst = sbB + (((BUF) * BN + row) * LDS_S + kc) * 4u;              \
            cp16(dst, src, p);                                                        \
        }                                                                             \
        asm volatile("cp.async.commit_group;\n");                                     \
    }

#define MATH(BUF)                                                                     \
    _Pragma("unroll")                                                                 \
    for (int kk = 0; kk < BK; kk += 8) {                                              \
        unsigned a[MI][4], b[NI][2];                                                  \
        _Pragma("unroll")                                                             \
        for (int mi = 0; mi < MI; ++mi) {                                             \
            int m0 = wm + mi * 16 + r0;                                               \
            const unsigned* ap0 = (const unsigned*)(Asm + ((BUF) * BM + m0) * LDS_S + kk + c0);      \
            const unsigned* ap1 = (const unsigned*)(Asm + ((BUF) * BM + m0 + 8) * LDS_S + kk + c0);  \
            a[mi][0] = ap0[0];                                                        \
            a[mi][1] = ap1[0];                                                        \
            a[mi][2] = ap0[4];                                                        \
            a[mi][3] = ap1[4];                                                        \
        }                                                                             \
        _Pragma("unroll")                                                             \
        for (int ni = 0; ni < NI; ++ni) {                                             \
            int n0 = wn + ni * 8 + r0;                                                \
            const unsigned* bp = (const unsigned*)(Bsm + ((BUF) * BN + n0) * LDS_S + kk + c0);       \
            b[ni][0] = bp[0];                                                         \
            b[ni][1] = bp[4];                                                         \
        }                                                                             \
        _Pragma("unroll")                                                             \
        for (int mi = 0; mi < MI; ++mi)                                               \
            _Pragma("unroll")                                                         \
            for (int ni = 0; ni < NI; ++ni)                                           \
                mma_tf32(acc[mi][ni], a[mi][0], a[mi][1], a[mi][2], a[mi][3],         \
                         b[ni][0], b[ni][1]);                                         \
    }

    int nt = D.K / BK;

#pragma unroll
    for (int s = 0; s < STAGES - 1; ++s) {
        if (s < nt) LOADSTAGE(s, s)
    }

    for (int t = 0; t < nt; ++t) {
        int lt = t + STAGES - 1;
        if (lt < nt) {
            LOADSTAGE(lt, lt % STAGES)
        } else {
            asm volatile("cp.async.commit_group;\n");
        }
        asm volatile("cp.async.wait_group %0;\n" :: "n"(STAGES - 1));
        __syncthreads();
        MATH(t % STAGES)
        __syncthreads();
    }

    // epilogue
#pragma unroll
    for (int mi = 0; mi < MI; ++mi) {
#pragma unroll
        for (int ni = 0; ni < NI; ++ni) {
            int cA = bn + wn + ni * 8 + c0 * 2;
            float b0 = 0.f, b1 = 0.f;
            if (D.bias) {
                if (cA < D.N)     b0 = D.bias[cA];
                if (cA + 1 < D.N) b1 = D.bias[cA + 1];
            }
#pragma unroll
            for (int half = 0; half < 2; ++half) {
                int r = bm + wm + mi * 16 + r0 + half * 8;
                if (r >= D.M) continue;
                float v0 = acc[mi][ni][half * 2]     + b0;
                float v1 = acc[mi][ni][half * 2 + 1] + b1;
                if (D.mode == 2) {
                    if (cA < D.N) {
                        C [(long long)r * D.ldc + cA] = tf32r(v0 + D.biasU[cA]);
                        C2[(long long)r * D.ldc + cA] = tf32r(v0 + D.biasV[cA]);
                    }
                    if (cA + 1 < D.N) {
                        C [(long long)r * D.ldc + cA + 1] = tf32r(v1 + D.biasU[cA + 1]);
                        C2[(long long)r * D.ldc + cA + 1] = tf32r(v1 + D.biasV[cA + 1]);
                    }
                } else {
                    if (D.roundC) { v0 = tf32r(v0); v1 = tf32r(v1); }
                    if (D.mode == 1) {
                        long long base = (long long)(r / LL) * HH;
                        int j = r % LL;
                        if (cA < D.N)     C[(base + cA) * LL + j]     = v0;
                        if (cA + 1 < D.N) C[(base + cA + 1) * LL + j] = v1;
                    } else {
                        if (cA < D.N)     C[(long long)r * D.ldc + cA]     = v0;
                        if (cA + 1 < D.N) C[(long long)r * D.ldc + cA + 1] = v1;
                    }
                }
            }
        }
    }
#undef LOADSTAGE
#undef MATH
}

// ---------------- softmax: merge S + shifted qR, scale+mask+exp+norm ----------------
__global__ void softmax_kernel(const int* __restrict__ seq_len)
{
    int bid = blockIdx.x;                 // (b*NH + h)*L + i
    int i = bid % LL;
    int b = bid / (LL * NHH);
    int tid = threadIdx.x;

    float*       Srow  = g_S  + (long long)bid * LL;
    const float* qRrow = g_qR + (long long)bid * RROWS + (MS - i);
    int sl = seq_len[b];

    float s[3];
    float m = -1e30f;
#pragma unroll
    for (int r = 0; r < 3; ++r) {
        int j = tid + r * 128;
        float v = (Srow[j] + qRrow[j]) * 0.125f;
        if (j >= sl) v = -1e30f;
        s[r] = v;
        m = fmaxf(m, v);
    }
    __shared__ float redm[4];
#pragma unroll
    for (int off = 16; off > 0; off >>= 1) m = fmaxf(m, __shfl_xor_sync(0xffffffffu, m, off));
    if ((tid & 31) == 0) redm[tid >> 5] = m;
    __syncthreads();
    m = fmaxf(fmaxf(redm[0], redm[1]), fmaxf(redm[2], redm[3]));

    float sum = 0.f;
#pragma unroll
    for (int r = 0; r < 3; ++r) { s[r] = __expf(s[r] - m); sum += s[r]; }
#pragma unroll
    for (int off = 16; off > 0; off >>= 1) sum += __shfl_xor_sync(0xffffffffu, sum, off);
    __shared__ float reds[4];
    if ((tid & 31) == 0) reds[tid >> 5] = sum;
    __syncthreads();
    sum = reds[0] + reds[1] + reds[2] + reds[3];
    float inv = 1.f / sum;
#pragma unroll
    for (int r = 0; r < 3; ++r) Srow[tid + r * 128] = tf32r(s[r] * inv);
}

// ------------------------------------ launch ------------------------------------------
extern "C" void kernel_launch(void* const* d_in, const int* in_sizes, int n_in,
                              void* d_out, int out_size)
{
    const float* key    = (const float*)d_in[0];
    const float* query  = (const float*)d_in[1];
    const float* value  = (const float*)d_in[2];
    const int*   seqlen = (const int*)  d_in[3];
    const float* pe     = (const float*)d_in[4];
    const float* Wk = (const float*)d_in[5];  const float* bk = (const float*)d_in[6];
    const float* Wq = (const float*)d_in[7];  const float* bq = (const float*)d_in[8];
    const float* Wv = (const float*)d_in[9];  const float* bv = (const float*)d_in[10];
    const float* Wr = (const float*)d_in[11]; const float* br = (const float*)d_in[12];
    const float* u_bias = (const float*)d_in[13];
    const float* v_bias = (const float*)d_in[14];
    const float* Wff = (const float*)d_in[15]; const float* bff = (const float*)d_in[16];
    float* out = (float*)d_out;

    float *qu_, *qv_, *k_, *vT_, *ctx_, *R_, *S_, *qR_;
    float *qin_, *kin_, *vin_, *pe_, *Wq_, *Wk_, *Wv_, *Wr_, *Wff_;
    cudaGetSymbolAddress((void**)&qu_,  g_qu);
    cudaGetSymbolAddress((void**)&qv_,  g_qv);
    cudaGetSymbolAddress((void**)&k_,   g_k);
    cudaGetSymbolAddress((void**)&vT_,  g_vT);
    cudaGetSymbolAddress((void**)&ctx_, g_ctx);
    cudaGetSymbolAddress((void**)&R_,   g_R);
    cudaGetSymbolAddress((void**)&S_,   g_S);
    cudaGetSymbolAddress((void**)&qR_,  g_qR);
    cudaGetSymbolAddress((void**)&qin_, g_qin);
    cudaGetSymbolAddress((void**)&kin_, g_kin);
    cudaGetSymbolAddress((void**)&vin_, g_vin);
    cudaGetSymbolAddress((void**)&pe_,  g_pe);
    cudaGetSymbolAddress((void**)&Wq_,  g_Wq);
    cudaGetSymbolAddress((void**)&Wk_,  g_Wk);
    cudaGetSymbolAddress((void**)&Wv_,  g_Wv);
    cudaGetSymbolAddress((void**)&Wr_,  g_Wr);
    cudaGetSymbolAddress((void**)&Wff_, g_Wff);

    const int M = BB * LL;   // 3072
    const size_t SH_BIG = (size_t)2 * (128 + 128) * 36 * 4;  // 73728 (2-stage BK=32)
    const size_t SH_AV  = (size_t)2 * (64 + 64)   * 36 * 4;  // 36864
    const size_t SH_FF  = (size_t)2 * (64 + 128)  * 36 * 4;  // 55296

    static bool attr_done = false;
    if (!attr_done) {
        cudaFuncSetAttribute(gemm_tc<128,128,64,32,32,2>,
                             cudaFuncAttributeMaxDynamicSharedMemorySize, (int)SH_BIG);
        cudaFuncSetAttribute(gemm_tc<64,64,32,16,32,2>,
                             cudaFuncAttributeMaxDynamicSharedMemorySize, (int)SH_AV);
        cudaFuncSetAttribute(gemm_tc<64,128,32,32,32,2>,
                             cudaFuncAttributeMaxDynamicSharedMemorySize, (int)SH_FF);
        attr_done = true;
    }

    // ---- 0) round all fp32 inputs to tf32 once ----
    {
        const int NXL = BB * LL * HH / 4;
        const int NPE = RROWS * HH / 4;
        const int NW  = HH * HH / 4;
        RPack P;
        P.s[0] = { query, qin_, NXL };
        P.s[1] = { key,   kin_, NXL };
        P.s[2] = { value, vin_, NXL };
        P.s[3] = { pe,    pe_,  NPE };
        P.s[4] = { Wq,    Wq_,  NW  };
        P.s[5] = { Wk,    Wk_,  NW  };
        P.s[6] = { Wv,    Wv_,  NW  };
        P.s[7] = { Wr,    Wr_,  NW  };
        P.s[8] = { Wff,   Wff_, NW  };
        int tot = 3 * NXL + NPE + 5 * NW;
        round_inputs<<<(tot + 255) / 256, 256>>>(P);
    }

    // ---- 1) projections: qu/qv (dual epilogue), k, vT (trans), R ----
    {
        GPack P;
        P.d[0] = { qin_, Wq_, bq, qu_, qv_, u_bias, v_bias,
                   M, HH, HH, HH, HH, HH, 0,0,0,0,0,0, 1, 1, 0, 2, 0 };
        P.d[1] = { kin_, Wk_, bk, k_,  nullptr, nullptr, nullptr,
                   M, HH, HH, HH, HH, HH, 0,0,0,0,0,0, 1, 1, 1, 0, 0 };
        P.d[2] = { vin_, Wv_, bv, vT_, nullptr, nullptr, nullptr,
                   M, HH, HH, HH, HH, HH, 0,0,0,0,0,0, 1, 1, 1, 1, 0 };
        P.d[3] = { pe_,  Wr_, br, R_,  nullptr, nullptr, nullptr,
                   RROWS, HH, HH, HH, HH, HH, 0,0,0,0,0,0, 1, 1, 1, 0, 0 };
        dim3 g(HH / 128, (M + 127) / 128, 4);
        gemm_tc<128,128,64,32,32,2><<<g, 256, SH_BIG>>>(P);
    }

    // ---- 2) A+C term and Bt+D term in one packed launch ----
    {
        GPack P;
        P.d[0] = { qu_, k_, nullptr, S_, nullptr, nullptr, nullptr,
                   LL, LL, DHH, HH, HH, LL,
                   (long long)LL * HH, DHH,
                   (long long)LL * HH, DHH,
                   (long long)NHH * LL * LL, (long long)LL * LL,
                   NHH, BB * NHH, 0, 0, 0 };
        P.d[1] = { qv_, R_, nullptr, qR_, nullptr, nullptr, nullptr,
                   LL, RROWS, DHH, HH, HH, RROWS,
                   (long long)LL * HH, DHH,
                   0, DHH,
                   (long long)NHH * LL * RROWS, (long long)LL * RROWS,
                   NHH, BB * NHH, 0, 0, 1 };
        P.d[2] = P.d[1]; P.d[3] = P.d[1];
        dim3 g((RROWS + 127) / 128, LL / 128, 2 * BB * NHH);
        gemm_tc<128,128,64,32,32,2><<<g, 256, SH_BIG>>>(P);
    }

    // ---- 3) softmax (S + shifted qR, scale+mask+exp+norm, round attn) ----
    softmax_kernel<<<BB * NHH * LL, 128>>>(seqlen);

    // ---- 4) AV: ctx = attn @ v_h  (64x64 tiles -> 384 CTAs) ----
    {
        GPack P;
        P.d[0] = { S_, vT_, nullptr, ctx_, nullptr, nullptr, nullptr,
                   LL, DHH, LL, LL, LL, HH,
                   (long long)NHH * LL * LL, (long long)LL * LL,
                   (long long)NHH * DHH * LL, (long long)DHH * LL,
                   (long long)LL * HH, DHH,
                   NHH, BB * NHH, 1, 0, 0 };
        P.d[1] = P.d[0]; P.d[2] = P.d[0]; P.d[3] = P.d[0];
        dim3 g(1, LL / 64, BB * NHH);
        gemm_tc<64,64,32,16,32,2><<<g, 256, SH_AV>>>(P);
    }

    // ---- 5) final FF: out = ctx @ Wff.T + bff (2-stage, 192 CTAs) ----
    {
        GPack P;
        P.d[0] = { ctx_, Wff_, bff, out, nullptr, nullptr, nullptr,
                   M, HH, HH, HH, HH, HH, 0,0,0,0,0,0, 1, 1, 0, 0, 0 };
        P.d[1] = P.d[0]; P.d[2] = P.d[0]; P.d[3] = P.d[0];
        dim3 g(HH / 128, (M + 63) / 64, 1);
        gemm_tc<64,128,32,32,32,2><<<g, 256, SH_FF>>>(P);
    }
}

// round 15
// speedup vs baseline: 1.0321x; 1.0119x over previous
#include <cuda_runtime.h>

#define BB   8
#define LL   384
#define HH   512
#define NHH  8
#define DHH  64
#define MS   384
#define RROWS 769

// ---------------- scratch (device globals; no allocation allowed) ----------------
__device__ float g_qu [BB*LL*HH];
__device__ float g_qv [BB*LL*HH];
__device__ float g_k  [BB*LL*HH];
__device__ float g_vT [BB*NHH*DHH*LL];
__device__ float g_ctx[BB*LL*HH];
__device__ float g_R  [RROWS*HH];
__device__ float g_S  [BB*NHH*LL*LL];
__device__ float g_qR [BB*NHH*LL*RROWS];
// rounded copies of raw inputs
__device__ float g_qin[BB*LL*HH];
__device__ float g_kin[BB*LL*HH];
__device__ float g_vin[BB*LL*HH];
__device__ float g_pe [RROWS*HH];
__device__ float g_Wq [HH*HH];
__device__ float g_Wk [HH*HH];
__device__ float g_Wv [HH*HH];
__device__ float g_Wr [HH*HH];
__device__ float g_Wff[HH*HH];

// ---------------- helpers ----------------
__device__ __forceinline__ float tf32r(float x) {
    unsigned u;
    asm("cvt.rna.tf32.f32 %0, %1;" : "=r"(u) : "f"(x));
    return __uint_as_float(u);
}

__device__ __forceinline__ void mma_tf32(float c[4],
                                         unsigned a0, unsigned a1, unsigned a2, unsigned a3,
                                         unsigned b0, unsigned b1)
{
    asm volatile(
        "mma.sync.aligned.m16n8k8.row.col.f32.tf32.tf32.f32 "
        "{%0,%1,%2,%3},{%4,%5,%6,%7},{%8,%9},{%0,%1,%2,%3};\n"
        : "+f"(c[0]), "+f"(c[1]), "+f"(c[2]), "+f"(c[3])
        : "r"(a0), "r"(a1), "r"(a2), "r"(a3), "r"(b0), "r"(b1));
}

__device__ __forceinline__ void cp16(unsigned dst, const void* src, bool pred) {
    int sz = pred ? 16 : 0;
    asm volatile("cp.async.cg.shared.global [%0], [%1], 16, %2;\n"
                 :: "r"(dst), "l"(src), "r"(sz));
}

// ---------------- pre-round pass: fp32 -> tf32(rna) copies ----------------
struct RSeg { const float* src; float* dst; int n4; };
struct RPack { RSeg s[9]; };

__global__ void round_inputs(RPack P)
{
    int idx = blockIdx.x * blockDim.x + threadIdx.x;
#pragma unroll
    for (int i = 0; i < 9; ++i) {
        if (idx < P.s[i].n4) {
            float4 v = ((const float4*)P.s[i].src)[idx];
            v.x = tf32r(v.x); v.y = tf32r(v.y); v.z = tf32r(v.z); v.w = tf32r(v.w);
            ((float4*)P.s[i].dst)[idx] = v;
            return;
        }
        idx -= P.s[i].n4;
    }
}

// ---------------- descriptor pack ----------------
// mode: 0 normal, 1 transC (v->vT), 2 qdual (write qu & qv with u/v biases)
// skewB: skip tiles outside the softmax band AND predicate stores to the band
struct GDesc {
    const float* A; const float* B; const float* bias; float* C;
    float* C2; const float* biasU; const float* biasV;
    int M, N, K, lda, ldb, ldc;
    long long Ao, Ai, Bo, Bi, Co, Ci;
    int bdiv;
    int zcount;
    int roundC;
    int mode;
    int skewB;
};
struct GPack { GDesc d[4]; };

// ---------------- tf32 tensor-core NT GEMM, parameterized pipeline ----------------
template<int BM, int BN, int WM, int WN, int BK, int STAGES>
__global__ void __launch_bounds__(256, 2)
gemm_tc(GPack P)
{
    constexpr int LDS_S = BK + 4;
    constexpr int WGM   = BM / WM;
    constexpr int MI    = WM / 16;
    constexpr int NI    = WN / 8;
    constexpr int CPR   = BK / 4;
    constexpr int ACH   = BM * CPR / 256;
    constexpr int BCH   = BN * CPR / 256;
    static_assert(WGM * (BN / WN) == 8, "8 warps");
    static_assert(BM * CPR % 256 == 0 && BN * CPR % 256 == 0, "even chunks");

    extern __shared__ float sm[];
    float* Asm = sm;
    float* Bsm = sm + STAGES * BM * LDS_S;
    unsigned sb  = (unsigned)__cvta_generic_to_shared(sm);
    unsigned sbB = sb + (unsigned)STAGES * BM * LDS_S * 4u;

    int zz = blockIdx.z;
    int di = 0;
    while (zz >= P.d[di].zcount) { zz -= P.d[di].zcount; ++di; }
    GDesc D = P.d[di];

    int bm = blockIdx.y * BM;
    int bn = blockIdx.x * BN;
    if (bm >= D.M || bn >= D.N) return;
    if (D.skewB) {
        int s = bm + bn;
        if (s + BM + BN - 2 < MS || s > MS + LL - 1) return;
    }

    const float* A = D.A + (long long)(zz / D.bdiv) * D.Ao + (long long)(zz % D.bdiv) * D.Ai;
    const float* B = D.B + (long long)(zz / D.bdiv) * D.Bo + (long long)(zz % D.bdiv) * D.Bi;
    float*       C = D.C + (long long)(zz / D.bdiv) * D.Co + (long long)(zz % D.bdiv) * D.Ci;
    float*       C2 = D.C2;

    int tid  = threadIdx.x;
    int lane = tid & 31;
    int wid  = tid >> 5;
    int wm   = (wid % WGM) * WM;
    int wn   = (wid / WGM) * WN;
    int r0   = lane >> 2;
    int c0   = lane & 3;

    float acc[MI][NI][4];
#pragma unroll
    for (int mi = 0; mi < MI; ++mi)
#pragma unroll
        for (int ni = 0; ni < NI; ++ni)
#pragma unroll
            for (int t = 0; t < 4; ++t) acc[mi][ni][t] = 0.f;

#define LOADSTAGE(T, BUF)                                                             \
    {                                                                                 \
        int kb = (T) * BK;                                                            \
        _Pragma("unroll")                                                             \
        for (int i = 0; i < ACH; ++i) {                                               \
            int e = tid + i * 256;                                                    \
            int row = e / CPR, kc = (e % CPR) * 4;                                    \
            bool p = (bm + row) < D.M;                                                \
            const float* src = A + (long long)(bm + row) * D.lda + kb + kc;           \
            unsigned dst = sb + (((BUF) * BM + row) * LDS_S + kc) * 4u;               \
            cp16(dst, src, p);                                                        \
        }                                                                             \
        _Pragma("unroll")                                                             \
        for (int i = 0; i < BCH; ++i) {                                               \
            int e = tid + i * 256;                                                    \
            int row = e / CPR, kc = (e % CPR) * 4;                                    \
            bool p = (bn + row) < D.N;                                                \
            const float* src = B + (long long)(bn + row) * D.ldb + kb + kc;           \
            unsigned dst = sbB + (((BUF) * BN + row) * LDS_S + kc) * 4u;              \
            cp16(dst, src, p);                                                        \
        }                                                                             \
        asm volatile("cp.async.commit_group;\n");                                     \
    }

#define MATH(BUF)                                                                     \
    _Pragma("unroll")                                                                 \
    for (int kk = 0; kk < BK; kk += 8) {                                              \
        unsigned a[MI][4], b[NI][2];                                                  \
        _Pragma("unroll")                                                             \
        for (int mi = 0; mi < MI; ++mi) {                                             \
            int m0 = wm + mi * 16 + r0;                                               \
            const unsigned* ap0 = (const unsigned*)(Asm + ((BUF) * BM + m0) * LDS_S + kk + c0);      \
            const unsigned* ap1 = (const unsigned*)(Asm + ((BUF) * BM + m0 + 8) * LDS_S + kk + c0);  \
            a[mi][0] = ap0[0];                                                        \
            a[mi][1] = ap1[0];                                                        \
            a[mi][2] = ap0[4];                                                        \
            a[mi][3] = ap1[4];                                                        \
        }                                                                             \
        _Pragma("unroll")                                                             \
        for (int ni = 0; ni < NI; ++ni) {                                             \
            int n0 = wn + ni * 8 + r0;                                                \
            const unsigned* bp = (const unsigned*)(Bsm + ((BUF) * BN + n0) * LDS_S + kk + c0);       \
            b[ni][0] = bp[0];                                                         \
            b[ni][1] = bp[4];                                                         \
        }                                                                             \
        _Pragma("unroll")                                                             \
        for (int mi = 0; mi < MI; ++mi)                                               \
            _Pragma("unroll")                                                         \
            for (int ni = 0; ni < NI; ++ni)                                           \
                mma_tf32(acc[mi][ni], a[mi][0], a[mi][1], a[mi][2], a[mi][3],         \
                         b[ni][0], b[ni][1]);                                         \
    }

    int nt = D.K / BK;

#pragma unroll
    for (int s = 0; s < STAGES - 1; ++s) {
        if (s < nt) LOADSTAGE(s, s)
    }

    for (int t = 0; t < nt; ++t) {
        int lt = t + STAGES - 1;
        if (lt < nt) {
            LOADSTAGE(lt, lt % STAGES)
        } else {
            asm volatile("cp.async.commit_group;\n");
        }
        asm volatile("cp.async.wait_group %0;\n" :: "n"(STAGES - 1));
        __syncthreads();
        MATH(t % STAGES)
        __syncthreads();
    }

    // epilogue
#pragma unroll
    for (int mi = 0; mi < MI; ++mi) {
#pragma unroll
        for (int ni = 0; ni < NI; ++ni) {
            int cA = bn + wn + ni * 8 + c0 * 2;
            float b0 = 0.f, b1 = 0.f;
            if (D.bias) {
                if (cA < D.N)     b0 = D.bias[cA];
                if (cA + 1 < D.N) b1 = D.bias[cA + 1];
            }
#pragma unroll
            for (int half = 0; half < 2; ++half) {
                int r = bm + wm + mi * 16 + r0 + half * 8;
                if (r >= D.M) continue;
                float v0 = acc[mi][ni][half * 2]     + b0;
                float v1 = acc[mi][ni][half * 2 + 1] + b1;
                if (D.mode == 2) {
                    if (cA < D.N) {
                        C [(long long)r * D.ldc + cA] = tf32r(v0 + D.biasU[cA]);
                        C2[(long long)r * D.ldc + cA] = tf32r(v0 + D.biasV[cA]);
                    }
                    if (cA + 1 < D.N) {
                        C [(long long)r * D.ldc + cA + 1] = tf32r(v1 + D.biasU[cA + 1]);
                        C2[(long long)r * D.ldc + cA + 1] = tf32r(v1 + D.biasV[cA + 1]);
                    }
                } else {
                    if (D.roundC) { v0 = tf32r(v0); v1 = tf32r(v1); }
                    if (D.mode == 1) {
                        long long base = (long long)(r / LL) * HH;
                        int j = r % LL;
                        if (cA < D.N)     C[(base + cA) * LL + j]     = v0;
                        if (cA + 1 < D.N) C[(base + cA + 1) * LL + j] = v1;
                    } else if (D.skewB) {
                        // qR[i, t] read only at j = t + i - MS in [0, LL)
                        int j0 = r + cA - MS;
                        if (cA < D.N && j0 >= 0 && j0 < LL)
                            C[(long long)r * D.ldc + cA] = v0;
                        if (cA + 1 < D.N && j0 + 1 >= 0 && j0 + 1 < LL)
                            C[(long long)r * D.ldc + cA + 1] = v1;
                    } else {
                        if (cA < D.N)     C[(long long)r * D.ldc + cA]     = v0;
                        if (cA + 1 < D.N) C[(long long)r * D.ldc + cA + 1] = v1;
                    }
                }
            }
        }
    }
#undef LOADSTAGE
#undef MATH
}

// ---------------- softmax: merge S + shifted qR, scale+mask+exp+norm ----------------
__global__ void softmax_kernel(const int* __restrict__ seq_len)
{
    int bid = blockIdx.x;                 // (b*NH + h)*L + i
    int i = bid % LL;
    int b = bid / (LL * NHH);
    int tid = threadIdx.x;

    float*       Srow  = g_S  + (long long)bid * LL;
    const float* qRrow = g_qR + (long long)bid * RROWS + (MS - i);
    int sl = seq_len[b];

    float s[3];
    float m = -1e30f;
#pragma unroll
    for (int r = 0; r < 3; ++r) {
        int j = tid + r * 128;
        float v = (Srow[j] + qRrow[j]) * 0.125f;
        if (j >= sl) v = -1e30f;
        s[r] = v;
        m = fmaxf(m, v);
    }
    __shared__ float redm[4];
#pragma unroll
    for (int off = 16; off > 0; off >>= 1) m = fmaxf(m, __shfl_xor_sync(0xffffffffu, m, off));
    if ((tid & 31) == 0) redm[tid >> 5] = m;
    __syncthreads();
    m = fmaxf(fmaxf(redm[0], redm[1]), fmaxf(redm[2], redm[3]));

    float sum = 0.f;
#pragma unroll
    for (int r = 0; r < 3; ++r) { s[r] = __expf(s[r] - m); sum += s[r]; }
#pragma unroll
    for (int off = 16; off > 0; off >>= 1) sum += __shfl_xor_sync(0xffffffffu, sum, off);
    __shared__ float reds[4];
    if ((tid & 31) == 0) reds[tid >> 5] = sum;
    __syncthreads();
    sum = reds[0] + reds[1] + reds[2] + reds[3];
    float inv = 1.f / sum;
#pragma unroll
    for (int r = 0; r < 3; ++r) Srow[tid + r * 128] = tf32r(s[r] * inv);
}

// ------------------------------------ launch ------------------------------------------
extern "C" void kernel_launch(void* const* d_in, const int* in_sizes, int n_in,
                              void* d_out, int out_size)
{
    const float* key    = (const float*)d_in[0];
    const float* query  = (const float*)d_in[1];
    const float* value  = (const float*)d_in[2];
    const int*   seqlen = (const int*)  d_in[3];
    const float* pe     = (const float*)d_in[4];
    const float* Wk = (const float*)d_in[5];  const float* bk = (const float*)d_in[6];
    const float* Wq = (const float*)d_in[7];  const float* bq = (const float*)d_in[8];
    const float* Wv = (const float*)d_in[9];  const float* bv = (const float*)d_in[10];
    const float* Wr = (const float*)d_in[11]; const float* br = (const float*)d_in[12];
    const float* u_bias = (const float*)d_in[13];
    const float* v_bias = (const float*)d_in[14];
    const float* Wff = (const float*)d_in[15]; const float* bff = (const float*)d_in[16];
    float* out = (float*)d_out;

    float *qu_, *qv_, *k_, *vT_, *ctx_, *R_, *S_, *qR_;
    float *qin_, *kin_, *vin_, *pe_, *Wq_, *Wk_, *Wv_, *Wr_, *Wff_;
    cudaGetSymbolAddress((void**)&qu_,  g_qu);
    cudaGetSymbolAddress((void**)&qv_,  g_qv);
    cudaGetSymbolAddress((void**)&k_,   g_k);
    cudaGetSymbolAddress((void**)&vT_,  g_vT);
    cudaGetSymbolAddress((void**)&ctx_, g_ctx);
    cudaGetSymbolAddress((void**)&R_,   g_R);
    cudaGetSymbolAddress((void**)&S_,   g_S);
    cudaGetSymbolAddress((void**)&qR_,  g_qR);
    cudaGetSymbolAddress((void**)&qin_, g_qin);
    cudaGetSymbolAddress((void**)&kin_, g_kin);
    cudaGetSymbolAddress((void**)&vin_, g_vin);
    cudaGetSymbolAddress((void**)&pe_,  g_pe);
    cudaGetSymbolAddress((void**)&Wq_,  g_Wq);
    cudaGetSymbolAddress((void**)&Wk_,  g_Wk);
    cudaGetSymbolAddress((void**)&Wv_,  g_Wv);
    cudaGetSymbolAddress((void**)&Wr_,  g_Wr);
    cudaGetSymbolAddress((void**)&Wff_, g_Wff);

    const int M = BB * LL;   // 3072
    const size_t SH_BIG = (size_t)2 * (128 + 128) * 36 * 4;  // 73728 (2-stage BK=32)
    const size_t SH_AV  = (size_t)2 * (128 + 64)  * 36 * 4;  // 55296
    const size_t SH_FF  = (size_t)2 * (64 + 128)  * 36 * 4;  // 55296

    static bool attr_done = false;
    if (!attr_done) {
        cudaFuncSetAttribute(gemm_tc<128,128,64,32,32,2>,
                             cudaFuncAttributeMaxDynamicSharedMemorySize, (int)SH_BIG);
        cudaFuncSetAttribute(gemm_tc<128,64,32,32,32,2>,
                             cudaFuncAttributeMaxDynamicSharedMemorySize, (int)SH_AV);
        cudaFuncSetAttribute(gemm_tc<64,128,32,32,32,2>,
                             cudaFuncAttributeMaxDynamicSharedMemorySize, (int)SH_FF);
        attr_done = true;
    }

    // ---- 0) round all fp32 inputs to tf32 once ----
    {
        const int NXL = BB * LL * HH / 4;
        const int NPE = RROWS * HH / 4;
        const int NW  = HH * HH / 4;
        RPack P;
        P.s[0] = { query, qin_, NXL };
        P.s[1] = { key,   kin_, NXL };
        P.s[2] = { value, vin_, NXL };
        P.s[3] = { pe,    pe_,  NPE };
        P.s[4] = { Wq,    Wq_,  NW  };
        P.s[5] = { Wk,    Wk_,  NW  };
        P.s[6] = { Wv,    Wv_,  NW  };
        P.s[7] = { Wr,    Wr_,  NW  };
        P.s[8] = { Wff,   Wff_, NW  };
        int tot = 3 * NXL + NPE + 5 * NW;
        round_inputs<<<(tot + 255) / 256, 256>>>(P);
    }

    // ---- 1) projections: qu/qv (dual epilogue), k, vT (trans), R ----
    {
        GPack P;
        P.d[0] = { qin_, Wq_, bq, qu_, qv_, u_bias, v_bias,
                   M, HH, HH, HH, HH, HH, 0,0,0,0,0,0, 1, 1, 0, 2, 0 };
        P.d[1] = { kin_, Wk_, bk, k_,  nullptr, nullptr, nullptr,
                   M, HH, HH, HH, HH, HH, 0,0,0,0,0,0, 1, 1, 1, 0, 0 };
        P.d[2] = { vin_, Wv_, bv, vT_, nullptr, nullptr, nullptr,
                   M, HH, HH, HH, HH, HH, 0,0,0,0,0,0, 1, 1, 1, 1, 0 };
        P.d[3] = { pe_,  Wr_, br, R_,  nullptr, nullptr, nullptr,
                   RROWS, HH, HH, HH, HH, HH, 0,0,0,0,0,0, 1, 1, 1, 0, 0 };
        dim3 g(HH / 128, (M + 127) / 128, 4);
        gemm_tc<128,128,64,32,32,2><<<g, 256, SH_BIG>>>(P);
    }

    // ---- 2) A+C term and Bt+D term in one packed launch (band-predicated qR) ----
    {
        GPack P;
        P.d[0] = { qu_, k_, nullptr, S_, nullptr, nullptr, nullptr,
                   LL, LL, DHH, HH, HH, LL,
                   (long long)LL * HH, DHH,
                   (long long)LL * HH, DHH,
                   (long long)NHH * LL * LL, (long long)LL * LL,
                   NHH, BB * NHH, 0, 0, 0 };
        P.d[1] = { qv_, R_, nullptr, qR_, nullptr, nullptr, nullptr,
                   LL, RROWS, DHH, HH, HH, RROWS,
                   (long long)LL * HH, DHH,
                   0, DHH,
                   (long long)NHH * LL * RROWS, (long long)LL * RROWS,
                   NHH, BB * NHH, 0, 0, 1 };
        P.d[2] = P.d[1]; P.d[3] = P.d[1];
        dim3 g((RROWS + 127) / 128, LL / 128, 2 * BB * NHH);
        gemm_tc<128,128,64,32,32,2><<<g, 256, SH_BIG>>>(P);
    }

    // ---- 3) softmax (S + shifted qR, scale+mask+exp+norm, round attn) ----
    softmax_kernel<<<BB * NHH * LL, 128>>>(seqlen);

    // ---- 4) AV: ctx = attn @ v_h  (128x64 tiles, 192 CTAs — R10 config) ----
    {
        GPack P;
        P.d[0] = { S_, vT_, nullptr, ctx_, nullptr, nullptr, nullptr,
                   LL, DHH, LL, LL, LL, HH,
                   (long long)NHH * LL * LL, (long long)LL * LL,
                   (long long)NHH * DHH * LL, (long long)DHH * LL,
                   (long long)LL * HH, DHH,
                   NHH, BB * NHH, 1, 0, 0 };
        P.d[1] = P.d[0]; P.d[2] = P.d[0]; P.d[3] = P.d[0];
        dim3 g(1, LL / 128, BB * NHH);
        gemm_tc<128,64,32,32,32,2><<<g, 256, SH_AV>>>(P);
    }

    // ---- 5) final FF: out = ctx @ Wff.T + bff (2-stage, 192 CTAs) ----
    {
        GPack P;
        P.d[0] = { ctx_, Wff_, bff, out, nullptr, nullptr, nullptr,
                   M, HH, HH, HH, HH, HH, 0,0,0,0,0,0, 1, 1, 0, 0, 0 };
        P.d[1] = P.d[0]; P.d[2] = P.d[0]; P.d[3] = P.d[0];
        dim3 g(HH / 128, (M + 63) / 64, 1);
        gemm_tc<64,128,32,32,32,2><<<g, 256, SH_FF>>>(P);
    }
}

// round 17
// speedup vs baseline: 1.0573x; 1.0244x over previous
#include <cuda_runtime.h>

#define BB   8
#define LL   384
#define HH   512
#define NHH  8
#define DHH  64
#define MS   384
#define RROWS 769

// ---------------- scratch (device globals; no allocation allowed) ----------------
__device__ float g_qu [BB*LL*HH];
__device__ float g_qv [BB*LL*HH];
__device__ float g_k  [BB*LL*HH];
__device__ float g_vT [BB*NHH*DHH*LL];
__device__ float g_ctx[BB*LL*HH];
__device__ float g_R  [RROWS*HH];
__device__ float g_S  [BB*NHH*LL*LL];
__device__ float g_qR [BB*NHH*LL*RROWS];   // used as [z][LL][LL] shifted buffer
// rounded copies of raw inputs
__device__ float g_qin[BB*LL*HH];
__device__ float g_kin[BB*LL*HH];
__device__ float g_vin[BB*LL*HH];
__device__ float g_pe [RROWS*HH];
__device__ float g_Wq [HH*HH];
__device__ float g_Wk [HH*HH];
__device__ float g_Wv [HH*HH];
__device__ float g_Wr [HH*HH];
__device__ float g_Wff[HH*HH];

// ---------------- helpers ----------------
__device__ __forceinline__ float tf32r(float x) {
    unsigned u;
    asm("cvt.rna.tf32.f32 %0, %1;" : "=r"(u) : "f"(x));
    return __uint_as_float(u);
}

__device__ __forceinline__ void mma_tf32(float c[4],
                                         unsigned a0, unsigned a1, unsigned a2, unsigned a3,
                                         unsigned b0, unsigned b1)
{
    asm volatile(
        "mma.sync.aligned.m16n8k8.row.col.f32.tf32.tf32.f32 "
        "{%0,%1,%2,%3},{%4,%5,%6,%7},{%8,%9},{%0,%1,%2,%3};\n"
        : "+f"(c[0]), "+f"(c[1]), "+f"(c[2]), "+f"(c[3])
        : "r"(a0), "r"(a1), "r"(a2), "r"(a3), "r"(b0), "r"(b1));
}

__device__ __forceinline__ void cp16(unsigned dst, const void* src, bool pred) {
    int sz = pred ? 16 : 0;
    asm volatile("cp.async.cg.shared.global [%0], [%1], 16, %2;\n"
                 :: "r"(dst), "l"(src), "r"(sz));
}

// ---------------- pre-round pass: fp32 -> tf32(rna) copies ----------------
struct RSeg { const float* src; float* dst; int n4; };
struct RPack { RSeg s[9]; };

__global__ void round_inputs(RPack P)
{
    int idx = blockIdx.x * blockDim.x + threadIdx.x;
#pragma unroll
    for (int i = 0; i < 9; ++i) {
        if (idx < P.s[i].n4) {
            float4 v = ((const float4*)P.s[i].src)[idx];
            v.x = tf32r(v.x); v.y = tf32r(v.y); v.z = tf32r(v.z); v.w = tf32r(v.w);
            ((float4*)P.s[i].dst)[idx] = v;
            return;
        }
        idx -= P.s[i].n4;
    }
}

// ---------------- descriptor pack ----------------
// mode: 0 normal, 1 transC (v->vT), 2 qdual (qu & qv with u/v biases),
//       4 shifted store: C[r][r + c - MS] = v (banded qR, aligned for softmax)
struct GDesc {
    const float* A; const float* B; const float* bias; float* C;
    float* C2; const float* biasU; const float* biasV;
    int M, N, K, lda, ldb, ldc;
    long long Ao, Ai, Bo, Bi, Co, Ci;
    int bdiv;
    int zcount;
    int roundC;
    int mode;
    int skewB;
};
struct GPack {
    GDesc d[4];
    int ntiles;              // if >0: compact tile list, grid.x = ntiles
    unsigned char tx[24];    // N-tile index
    unsigned char ty[24];    // M-tile index
    unsigned char td[24];    // descriptor index
};

// ---------------- tf32 tensor-core NT GEMM, parameterized pipeline ----------------
template<int BM, int BN, int WM, int WN, int BK, int STAGES>
__global__ void __launch_bounds__(256, 2)
gemm_tc(GPack P)
{
    constexpr int LDS_S = BK + 4;
    constexpr int WGM   = BM / WM;
    constexpr int MI    = WM / 16;
    constexpr int NI    = WN / 8;
    constexpr int CPR   = BK / 4;
    constexpr int ACH   = BM * CPR / 256;
    constexpr int BCH   = BN * CPR / 256;
    static_assert(WGM * (BN / WN) == 8, "8 warps");
    static_assert(BM * CPR % 256 == 0 && BN * CPR % 256 == 0, "even chunks");

    extern __shared__ float sm[];
    float* Asm = sm;
    float* Bsm = sm + STAGES * BM * LDS_S;
    unsigned sb  = (unsigned)__cvta_generic_to_shared(sm);
    unsigned sbB = sb + (unsigned)STAGES * BM * LDS_S * 4u;

    int di, bm, bn, zz;
    if (P.ntiles) {
        int t = blockIdx.x;
        di = P.td[t];
        bn = P.tx[t] * BN;
        bm = P.ty[t] * BM;
        zz = blockIdx.z;
    } else {
        zz = blockIdx.z;
        di = 0;
        while (zz >= P.d[di].zcount) { zz -= P.d[di].zcount; ++di; }
        bm = blockIdx.y * BM;
        bn = blockIdx.x * BN;
    }
    GDesc D = P.d[di];

    if (bm >= D.M || bn >= D.N) return;
    if (D.skewB) {
        int s = bm + bn;
        if (s + BM + BN - 2 < MS || s > MS + LL - 1) return;
    }

    const float* A = D.A + (long long)(zz / D.bdiv) * D.Ao + (long long)(zz % D.bdiv) * D.Ai;
    const float* B = D.B + (long long)(zz / D.bdiv) * D.Bo + (long long)(zz % D.bdiv) * D.Bi;
    float*       C = D.C + (long long)(zz / D.bdiv) * D.Co + (long long)(zz % D.bdiv) * D.Ci;
    float*       C2 = D.C2;

    int tid  = threadIdx.x;
    int lane = tid & 31;
    int wid  = tid >> 5;
    int wm   = (wid % WGM) * WM;
    int wn   = (wid / WGM) * WN;
    int r0   = lane >> 2;
    int c0   = lane & 3;

    float acc[MI][NI][4];
#pragma unroll
    for (int mi = 0; mi < MI; ++mi)
#pragma unroll
        for (int ni = 0; ni < NI; ++ni)
#pragma unroll
            for (int t = 0; t < 4; ++t) acc[mi][ni][t] = 0.f;

#define LOADSTAGE(T, BUF)                                                             \
    {                                                                                 \
        int kb = (T) * BK;                                                            \
        _Pragma("unroll")                                                             \
        for (int i = 0; i < ACH; ++i) {                                               \
            int e = tid + i * 256;                                                    \
            int row = e / CPR, kc = (e % CPR) * 4;                                    \
            bool p = (bm + row) < D.M;                                                \
            const float* src = A + (long long)(bm + row) * D.lda + kb + kc;           \
            unsigned dst = sb + (((BUF) * BM + row) * LDS_S + kc) * 4u;               \
            cp16(dst, src, p);                                                        \
        }                                                                             \
        _Pragma("unroll")                                                             \
        for (int i = 0; i < BCH; ++i) {                                               \
            int e = tid + i * 256;                                                    \
            int row = e / CPR, kc = (e % CPR) * 4;                                    \
            bool p = (bn + row) < D.N;                                                \
            const float* src = B + (long long)(bn + row) * D.ldb + kb + kc;           \
            unsigned dst = sbB + (((BUF) * BN + row) * LDS_S + kc) * 4u;              \
            cp16(dst, src, p);                                                        \
        }                                                                             \
        asm volatile("cp.async.commit_group;\n");                                     \
    }

#define MATH(BUF)                                                                     \
    _Pragma("unroll")                                                                 \
    for (int kk = 0; kk < BK; kk += 8) {                                              \
        unsigned a[MI][4], b[NI][2];                                                  \
        _Pragma("unroll")                                                             \
        for (int mi = 0; mi < MI; ++mi) {                                             \
            int m0 = wm + mi * 16 + r0;                                               \
            const unsigned* ap0 = (const unsigned*)(Asm + ((BUF) * BM + m0) * LDS_S + kk + c0);      \
            const unsigned* ap1 = (const unsigned*)(Asm + ((BUF) * BM + m0 + 8) * LDS_S + kk + c0);  \
            a[mi][0] = ap0[0];                                                        \
            a[mi][1] = ap1[0];                                                        \
            a[mi][2] = ap0[4];                                                        \
            a[mi][3] = ap1[4];                                                        \
        }                                                                             \
        _Pragma("unroll")                                                             \
        for (int ni = 0; ni < NI; ++ni) {                                             \
            int n0 = wn + ni * 8 + r0;                                                \
            const unsigned* bp = (const unsigned*)(Bsm + ((BUF) * BN + n0) * LDS_S + kk + c0);       \
            b[ni][0] = bp[0];                                                         \
            b[ni][1] = bp[4];                                                         \
        }                                                                             \
        _Pragma("unroll")                                                             \
        for (int mi = 0; mi < MI; ++mi)                                               \
            _Pragma("unroll")                                                         \
            for (int ni = 0; ni < NI; ++ni)                                           \
                mma_tf32(acc[mi][ni], a[mi][0], a[mi][1], a[mi][2], a[mi][3],         \
                         b[ni][0], b[ni][1]);                                         \
    }

    int nt = D.K / BK;

#pragma unroll
    for (int s = 0; s < STAGES - 1; ++s) {
        if (s < nt) LOADSTAGE(s, s)
    }

    for (int t = 0; t < nt; ++t) {
        int lt = t + STAGES - 1;
        if (lt < nt) {
            LOADSTAGE(lt, lt % STAGES)
        } else {
            asm volatile("cp.async.commit_group;\n");
        }
        asm volatile("cp.async.wait_group %0;\n" :: "n"(STAGES - 1));
        __syncthreads();
        MATH(t % STAGES)
        __syncthreads();
    }

    // epilogue
#pragma unroll
    for (int mi = 0; mi < MI; ++mi) {
#pragma unroll
        for (int ni = 0; ni < NI; ++ni) {
            int cA = bn + wn + ni * 8 + c0 * 2;
            float b0 = 0.f, b1 = 0.f;
            if (D.bias) {
                if (cA < D.N)     b0 = D.bias[cA];
                if (cA + 1 < D.N) b1 = D.bias[cA + 1];
            }
#pragma unroll
            for (int half = 0; half < 2; ++half) {
                int r = bm + wm + mi * 16 + r0 + half * 8;
                if (r >= D.M) continue;
                float v0 = acc[mi][ni][half * 2]     + b0;
                float v1 = acc[mi][ni][half * 2 + 1] + b1;
                if (D.mode == 2) {
                    if (cA < D.N) {
                        C [(long long)r * D.ldc + cA] = tf32r(v0 + D.biasU[cA]);
                        C2[(long long)r * D.ldc + cA] = tf32r(v0 + D.biasV[cA]);
                    }
                    if (cA + 1 < D.N) {
                        C [(long long)r * D.ldc + cA + 1] = tf32r(v1 + D.biasU[cA + 1]);
                        C2[(long long)r * D.ldc + cA + 1] = tf32r(v1 + D.biasV[cA + 1]);
                    }
                } else if (D.mode == 4) {
                    // banded shifted store: C[r][j], j = cA + r - MS, row-contiguous
                    int j0 = r + cA - MS;
                    if (cA < D.N && j0 >= 0 && j0 < LL)
                        C[(long long)r * D.ldc + j0] = v0;
                    if (cA + 1 < D.N && j0 + 1 >= 0 && j0 + 1 < LL)
                        C[(long long)r * D.ldc + j0 + 1] = v1;
                } else {
                    if (D.roundC) { v0 = tf32r(v0); v1 = tf32r(v1); }
                    if (D.mode == 1) {
                        long long base = (long long)(r / LL) * HH;
                        int j = r % LL;
                        if (cA < D.N)     C[(base + cA) * LL + j]     = v0;
                        if (cA + 1 < D.N) C[(base + cA + 1) * LL + j] = v1;
                    } else {
                        if (cA < D.N)     C[(long long)r * D.ldc + cA]     = v0;
                        if (cA + 1 < D.N) C[(long long)r * D.ldc + cA + 1] = v1;
                    }
                }
            }
        }
    }
#undef LOADSTAGE
#undef MATH
}

// ---------------- softmax: S + aligned shifted qR, scale+mask+exp+norm ----------------
__global__ void softmax_kernel(const int* __restrict__ seq_len)
{
    int bid = blockIdx.x;                 // (b*NH + h)*L + i
    int b = bid / (LL * NHH);
    int tid = threadIdx.x;

    float*       Srow  = g_S  + (long long)bid * LL;
    const float* qRrow = g_qR + (long long)bid * LL;   // shifted buffer, aligned
    int sl = seq_len[b];

    float s[3];
    float m = -1e30f;
#pragma unroll
    for (int r = 0; r < 3; ++r) {
        int j = tid + r * 128;
        float v = (Srow[j] + qRrow[j]) * 0.125f;
        if (j >= sl) v = -1e30f;
        s[r] = v;
        m = fmaxf(m, v);
    }
    __shared__ float redm[4];
#pragma unroll
    for (int off = 16; off > 0; off >>= 1) m = fmaxf(m, __shfl_xor_sync(0xffffffffu, m, off));
    if ((tid & 31) == 0) redm[tid >> 5] = m;
    __syncthreads();
    m = fmaxf(fmaxf(redm[0], redm[1]), fmaxf(redm[2], redm[3]));

    float sum = 0.f;
#pragma unroll
    for (int r = 0; r < 3; ++r) { s[r] = __expf(s[r] - m); sum += s[r]; }
#pragma unroll
    for (int off = 16; off > 0; off >>= 1) sum += __shfl_xor_sync(0xffffffffu, sum, off);
    __shared__ float reds[4];
    if ((tid & 31) == 0) reds[tid >> 5] = sum;
    __syncthreads();
    sum = reds[0] + reds[1] + reds[2] + reds[3];
    float inv = 1.f / sum;
#pragma unroll
    for (int r = 0; r < 3; ++r) Srow[tid + r * 128] = tf32r(s[r] * inv);
}

// ------------------------------------ launch ------------------------------------------
extern "C" void kernel_launch(void* const* d_in, const int* in_sizes, int n_in,
                              void* d_out, int out_size)
{
    const float* key    = (const float*)d_in[0];
    const float* query  = (const float*)d_in[1];
    const float* value  = (const float*)d_in[2];
    const int*   seqlen = (const int*)  d_in[3];
    const float* pe     = (const float*)d_in[4];
    const float* Wk = (const float*)d_in[5];  const float* bk = (const float*)d_in[6];
    const float* Wq = (const float*)d_in[7];  const float* bq = (const float*)d_in[8];
    const float* Wv = (const float*)d_in[9];  const float* bv = (const float*)d_in[10];
    const float* Wr = (const float*)d_in[11]; const float* br = (const float*)d_in[12];
    const float* u_bias = (const float*)d_in[13];
    const float* v_bias = (const float*)d_in[14];
    const float* Wff = (const float*)d_in[15]; const float* bff = (const float*)d_in[16];
    float* out = (float*)d_out;

    float *qu_, *qv_, *k_, *vT_, *ctx_, *R_, *S_, *qR_;
    float *qin_, *kin_, *vin_, *pe_, *Wq_, *Wk_, *Wv_, *Wr_, *Wff_;
    cudaGetSymbolAddress((void**)&qu_,  g_qu);
    cudaGetSymbolAddress((void**)&qv_,  g_qv);
    cudaGetSymbolAddress((void**)&k_,   g_k);
    cudaGetSymbolAddress((void**)&vT_,  g_vT);
    cudaGetSymbolAddress((void**)&ctx_, g_ctx);
    cudaGetSymbolAddress((void**)&R_,   g_R);
    cudaGetSymbolAddress((void**)&S_,   g_S);
    cudaGetSymbolAddress((void**)&qR_,  g_qR);
    cudaGetSymbolAddress((void**)&qin_, g_qin);
    cudaGetSymbolAddress((void**)&kin_, g_kin);
    cudaGetSymbolAddress((void**)&vin_, g_vin);
    cudaGetSymbolAddress((void**)&pe_,  g_pe);
    cudaGetSymbolAddress((void**)&Wq_,  g_Wq);
    cudaGetSymbolAddress((void**)&Wk_,  g_Wk);
    cudaGetSymbolAddress((void**)&Wv_,  g_Wv);
    cudaGetSymbolAddress((void**)&Wr_,  g_Wr);
    cudaGetSymbolAddress((void**)&Wff_, g_Wff);

    const int M = BB * LL;   // 3072
    const size_t SH_BIG = (size_t)2 * (128 + 128) * 36 * 4;  // 73728 (2-stage BK=32)
    const size_t SH_AV  = (size_t)2 * (128 + 64)  * 36 * 4;  // 55296
    const size_t SH_FF  = (size_t)2 * (64 + 128)  * 36 * 4;  // 55296

    static bool attr_done = false;
    if (!attr_done) {
        cudaFuncSetAttribute(gemm_tc<128,128,64,32,32,2>,
                             cudaFuncAttributeMaxDynamicSharedMemorySize, (int)SH_BIG);
        cudaFuncSetAttribute(gemm_tc<128,64,32,32,32,2>,
                             cudaFuncAttributeMaxDynamicSharedMemorySize, (int)SH_AV);
        cudaFuncSetAttribute(gemm_tc<64,128,32,32,32,2>,
                             cudaFuncAttributeMaxDynamicSharedMemorySize, (int)SH_FF);
        attr_done = true;
    }

    // ---- 0) round all fp32 inputs to tf32 once ----
    {
        const int NXL = BB * LL * HH / 4;
        const int NPE = RROWS * HH / 4;
        const int NW  = HH * HH / 4;
        RPack P;
        P.s[0] = { query, qin_, NXL };
        P.s[1] = { key,   kin_, NXL };
        P.s[2] = { value, vin_, NXL };
        P.s[3] = { pe,    pe_,  NPE };
        P.s[4] = { Wq,    Wq_,  NW  };
        P.s[5] = { Wk,    Wk_,  NW  };
        P.s[6] = { Wv,    Wv_,  NW  };
        P.s[7] = { Wr,    Wr_,  NW  };
        P.s[8] = { Wff,   Wff_, NW  };
        int tot = 3 * NXL + NPE + 5 * NW;
        round_inputs<<<(tot + 255) / 256, 256>>>(P);
    }

    // ---- 1) projections: qu/qv (dual epilogue), k, vT (trans), R ----
    {
        GPack P = {};
        P.d[0] = { qin_, Wq_, bq, qu_, qv_, u_bias, v_bias,
                   M, HH, HH, HH, HH, HH, 0,0,0,0,0,0, 1, 1, 0, 2, 0 };
        P.d[1] = { kin_, Wk_, bk, k_,  nullptr, nullptr, nullptr,
                   M, HH, HH, HH, HH, HH, 0,0,0,0,0,0, 1, 1, 1, 0, 0 };
        P.d[2] = { vin_, Wv_, bv, vT_, nullptr, nullptr, nullptr,
                   M, HH, HH, HH, HH, HH, 0,0,0,0,0,0, 1, 1, 1, 1, 0 };
        P.d[3] = { pe_,  Wr_, br, R_,  nullptr, nullptr, nullptr,
                   RROWS, HH, HH, HH, HH, HH, 0,0,0,0,0,0, 1, 1, 1, 0, 0 };
        P.ntiles = 0;
        dim3 g(HH / 128, (M + 127) / 128, 4);
        gemm_tc<128,128,64,32,32,2><<<g, 256, SH_BIG>>>(P);
    }

    // ---- 2) A+C and Bt+D in one COMPACT launch (tile LUT; Bt stores shifted) ----
    {
        GPack P = {};
        P.d[0] = { qu_, k_, nullptr, S_, nullptr, nullptr, nullptr,
                   LL, LL, DHH, HH, HH, LL,
                   (long long)LL * HH, DHH,
                   (long long)LL * HH, DHH,
                   (long long)NHH * LL * LL, (long long)LL * LL,
                   NHH, BB * NHH, 0, 0, 0 };
        // Bt: output shifted-banded into qR as [z][LL][LL]
        P.d[1] = { qv_, R_, nullptr, qR_, nullptr, nullptr, nullptr,
                   LL, RROWS, DHH, HH, HH, LL,
                   (long long)LL * HH, DHH,
                   0, DHH,
                   (long long)NHH * LL * LL, (long long)LL * LL,
                   NHH, BB * NHH, 0, 4, 0 };
        P.d[2] = P.d[1]; P.d[3] = P.d[1];
        int n = 0;
        // A tiles: 3x3
        for (int by = 0; by < 3; ++by)
            for (int bx = 0; bx < 3; ++bx) {
                P.tx[n] = bx; P.ty[n] = by; P.td[n] = 0; ++n;
            }
        // Bt band tiles: bx in 0..6 (N=769 -> 7 tiles), by in 0..2, bx+by in [2,5]
        for (int by = 0; by < 3; ++by)
            for (int bx = 0; bx < 7; ++bx) {
                int s = bx + by;
                if (s >= 2 && s <= 5) { P.tx[n] = bx; P.ty[n] = by; P.td[n] = 1; ++n; }
            }
        P.ntiles = n;   // 21
        dim3 g(n, 1, BB * NHH);
        gemm_tc<128,128,64,32,32,2><<<g, 256, SH_BIG>>>(P);
    }

    // ---- 3) softmax (S + aligned qR, scale+mask+exp+norm, round attn) ----
    softmax_kernel<<<BB * NHH * LL, 128>>>(seqlen);

    // ---- 4) AV: ctx = attn @ v_h  (128x64 tiles, 192 CTAs) ----
    {
        GPack P = {};
        P.d[0] = { S_, vT_, nullptr, ctx_, nullptr, nullptr, nullptr,
                   LL, DHH, LL, LL, LL, HH,
                   (long long)NHH * LL * LL, (long long)LL * LL,
                   (long long)NHH * DHH * LL, (long long)DHH * LL,
                   (long long)LL * HH, DHH,
                   NHH, BB * NHH, 1, 0, 0 };
        P.d[1] = P.d[0]; P.d[2] = P.d[0]; P.d[3] = P.d[0];
        P.ntiles = 0;
        dim3 g(1, LL / 128, BB * NHH);
        gemm_tc<128,64,32,32,32,2><<<g, 256, SH_AV>>>(P);
    }

    // ---- 5) final FF: out = ctx @ Wff.T + bff (2-stage, 192 CTAs) ----
    {
        GPack P = {};
        P.d[0] = { ctx_, Wff_, bff, out, nullptr, nullptr, nullptr,
                   M, HH, HH, HH, HH, HH, 0,0,0,0,0,0, 1, 1, 0, 0, 0 };
        P.d[1] = P.d[0]; P.d[2] = P.d[0]; P.d[3] = P.d[0];
        P.ntiles = 0;
        dim3 g(HH / 128, (M + 63) / 64, 1);
        gemm_tc<64,128,32,32,32,2><<<g, 256, SH_FF>>>(P);
    }
}